// round 6
// baseline (speedup 1.0000x reference)
#include <cuda_runtime.h>
#include <cuda_bf16.h>

#define B_CONST 32
#define L_CONST 256
#define H_CONST 512

// Scratch (no allocations allowed anywhere)
__device__ int g_csum[B_CONST * L_CONST];   // inclusive cumsum of durations
__device__ int g_total[B_CONST];

// Kernel 1: per-batch parallel scan -> g_csum/g_total, plus coalesced mask.
__global__ void __launch_bounds__(L_CONST) build_kernel(
    const int* __restrict__ dur,
    float* __restrict__ out_mask,   // [B, T]
    int T)
{
    __shared__ int s_wsum[8];
    __shared__ int s_total;

    int b    = blockIdx.x;
    int l    = threadIdx.x;
    int lane = l & 31;
    int w    = l >> 5;

    int d = dur[b * L_CONST + l];

    // warp inclusive scan
    int v = d;
    #pragma unroll
    for (int off = 1; off < 32; off <<= 1) {
        int n = __shfl_up_sync(0xFFFFFFFFu, v, off);
        if (lane >= off) v += n;
    }
    if (lane == 31) s_wsum[w] = v;
    __syncthreads();

    if (w == 0) {
        int ws = (lane < 8) ? s_wsum[lane] : 0;
        #pragma unroll
        for (int off = 1; off < 8; off <<= 1) {
            int n = __shfl_up_sync(0xFFFFFFFFu, ws, off);
            if (lane >= off) ws += n;
        }
        if (lane < 8) s_wsum[lane] = ws;
        if (lane == 7) s_total = ws;
    }
    __syncthreads();

    int base = (w > 0) ? s_wsum[w - 1] : 0;
    g_csum[b * L_CONST + l] = base + v;
    if (l == 0) g_total[b] = s_total;

    // mask 0.0/1.0 (coalesced)
    float* m = out_mask + (size_t)b * T;
    int total = s_total;
    for (int t = l; t < T; t += L_CONST) m[t] = (t < total) ? 1.0f : 0.0f;
}

// Kernel 2: source-centric scatter. Warp u < L: load source row l=u ONCE
// (4 float4/thread), stream-store it to output rows [csum[l-1], csum[l]).
// Warp u >= L: zero tail row t = u - L if t >= total (masked region).
__global__ void __launch_bounds__(256) expand_kernel(
    const float4* __restrict__ x4,   // [B, L, 128]
    float4* __restrict__ out4,       // [B, T, 128]
    int T)
{
    int u    = (blockIdx.x * 256 + threadIdx.x) >> 5;  // warp index within batch
    int lane = threadIdx.x & 31;
    int b    = blockIdx.y;

    if (u < L_CONST) {
        int l     = u;
        int end   = g_csum[b * L_CONST + l];                       // warp-uniform
        int start = (l > 0) ? g_csum[b * L_CONST + l - 1] : 0;
        if (start == end) return;

        const float4* s = x4 + ((size_t)b * L_CONST + l) * 128 + lane;
        float4 v0 = __ldg(s);
        float4 v1 = __ldg(s + 32);
        float4 v2 = __ldg(s + 64);
        float4 v3 = __ldg(s + 96);

        float4* d = out4 + ((size_t)b * T + start) * 128 + lane;
        int t = start;
        // 2 rows per iteration: 8 independent streaming stores in flight
        for (; t + 1 < end; t += 2, d += 256) {
            __stcs(d,        v0);
            __stcs(d + 32,   v1);
            __stcs(d + 64,   v2);
            __stcs(d + 96,   v3);
            __stcs(d + 128,  v0);
            __stcs(d + 160,  v1);
            __stcs(d + 192,  v2);
            __stcs(d + 224,  v3);
        }
        if (t < end) {
            __stcs(d,       v0);
            __stcs(d + 32,  v1);
            __stcs(d + 64,  v2);
            __stcs(d + 96,  v3);
        }
    } else {
        int t = u - L_CONST;
        if (t >= T) return;
        if (t < g_total[b]) return;          // inside valid region -> nothing
        float4 z = make_float4(0.f, 0.f, 0.f, 0.f);
        float4* d = out4 + ((size_t)b * T + t) * 128 + lane;
        __stcs(d,       z);
        __stcs(d + 32,  z);
        __stcs(d + 64,  z);
        __stcs(d + 96,  z);
    }
}

extern "C" void kernel_launch(void* const* d_in, const int* in_sizes, int n_in,
                              void* d_out, int out_size) {
    const float* x;
    const int*   dur;
    if (in_sizes[0] == B_CONST * L_CONST) {
        dur = (const int*)d_in[0];
        x   = (const float*)d_in[1];
    } else {
        x   = (const float*)d_in[0];
        dur = (const int*)d_in[1];
    }

    int T = out_size / (B_CONST * (H_CONST + 1));

    float* out      = (float*)d_out;
    float* out_mask = out + (size_t)B_CONST * T * H_CONST;

    build_kernel<<<B_CONST, L_CONST>>>(dur, out_mask, T);

    int warps_per_batch   = L_CONST + T;      // scatter warps + tail-zero warps
    int threads_per_batch = warps_per_batch * 32;
    dim3 grid((threads_per_batch + 255) / 256, B_CONST);
    expand_kernel<<<grid, 256>>>(
        (const float4*)x, (float4*)out, T);
}

// round 7
// speedup vs baseline: 1.2007x; 1.2007x over previous
#include <cuda_runtime.h>
#include <cuda_bf16.h>

#define B_CONST 32
#define L_CONST 256
#define H_CONST 512
#define T_MAX   8192     // durations < 16, L=256 -> total < 4096; headroom
#define ROWS_PER_WARP 4

// Scratch (no allocations allowed anywhere)
__device__ int g_idx[B_CONST * T_MAX];   // source index per output frame, -1 = masked

// Kernel 1: per-batch parallel scan + scatter of index table + mask.
__global__ void __launch_bounds__(L_CONST) build_idx_kernel(
    const int* __restrict__ dur,
    float* __restrict__ out_mask,   // [B, T]
    int T)
{
    __shared__ int s_wsum[8];
    __shared__ int s_total;

    int b    = blockIdx.x;
    int l    = threadIdx.x;
    int lane = l & 31;
    int w    = l >> 5;

    int d = dur[b * L_CONST + l];

    // warp inclusive scan
    int v = d;
    #pragma unroll
    for (int off = 1; off < 32; off <<= 1) {
        int n = __shfl_up_sync(0xFFFFFFFFu, v, off);
        if (lane >= off) v += n;
    }
    if (lane == 31) s_wsum[w] = v;
    __syncthreads();

    if (w == 0) {
        int ws = (lane < 8) ? s_wsum[lane] : 0;
        #pragma unroll
        for (int off = 1; off < 8; off <<= 1) {
            int n = __shfl_up_sync(0xFFFFFFFFu, ws, off);
            if (lane >= off) ws += n;
        }
        if (lane < 8) s_wsum[lane] = ws;
        if (lane == 7) s_total = ws;
    }
    __syncthreads();

    int base  = (w > 0) ? s_wsum[w - 1] : 0;
    int end   = base + v;       // inclusive csum[l]
    int start = end - d;
    int total = s_total;

    int* idx = g_idx + b * T_MAX;
    for (int t = start; t < end; ++t) idx[t] = l;
    for (int t = total + l; t < T; t += L_CONST) idx[t] = -1;

    float* m = out_mask + (size_t)b * T;
    for (int t = l; t < T; t += L_CONST) m[t] = (t < total) ? 1.0f : 0.0f;
}

// Kernel 2: gather-copy with source dedup. One warp per 4 consecutive output
// rows; the 2KB source row is (re)loaded only when idx changes between rows
// (~87% of consecutive rows share a source), cutting L2 read traffic ~3x.
// Stores are streaming (__stcs) so x stays L2-resident.
__global__ void __launch_bounds__(256) expand_kernel(
    const float4* __restrict__ x4,   // [B, L, 128]
    float4* __restrict__ out4,       // [B, T, 128]
    int T)
{
    int wid  = (blockIdx.x * 256 + threadIdx.x) >> 5;   // warp id within batch
    int lane = threadIdx.x & 31;
    int b    = blockIdx.y;

    int t0 = wid * ROWS_PER_WARP;
    if (t0 >= T) return;

    const int* idxp = g_idx + b * T_MAX;

    const float4 z = make_float4(0.f, 0.f, 0.f, 0.f);
    float4 v0 = z, v1 = z, v2 = z, v3 = z;
    int cur = -2;                                        // nothing loaded yet

    float4* d = out4 + ((size_t)b * T + t0) * 128 + lane;

    #pragma unroll
    for (int r = 0; r < ROWS_PER_WARP; ++r) {
        int t = t0 + r;
        if (t >= T) break;
        int idx = idxp[t];                               // warp-uniform
        if (idx != cur) {
            if (idx >= 0) {
                const float4* s = x4 + ((size_t)b * L_CONST + idx) * 128 + lane;
                v0 = __ldg(s);
                v1 = __ldg(s + 32);
                v2 = __ldg(s + 64);
                v3 = __ldg(s + 96);
            } else {
                v0 = z; v1 = z; v2 = z; v3 = z;
            }
            cur = idx;
        }
        __stcs(d,      v0);
        __stcs(d + 32, v1);
        __stcs(d + 64, v2);
        __stcs(d + 96, v3);
        d += 128;
    }
}

extern "C" void kernel_launch(void* const* d_in, const int* in_sizes, int n_in,
                              void* d_out, int out_size) {
    const float* x;
    const int*   dur;
    if (in_sizes[0] == B_CONST * L_CONST) {
        dur = (const int*)d_in[0];
        x   = (const float*)d_in[1];
    } else {
        x   = (const float*)d_in[0];
        dur = (const int*)d_in[1];
    }

    int T = out_size / (B_CONST * (H_CONST + 1));

    float* out      = (float*)d_out;
    float* out_mask = out + (size_t)B_CONST * T * H_CONST;

    build_idx_kernel<<<B_CONST, L_CONST>>>(dur, out_mask, T);

    int warps_per_batch   = (T + ROWS_PER_WARP - 1) / ROWS_PER_WARP;
    int threads_per_batch = warps_per_batch * 32;
    dim3 grid((threads_per_batch + 255) / 256, B_CONST);
    expand_kernel<<<grid, 256>>>(
        (const float4*)x, (float4*)out, T);
}

// round 9
// speedup vs baseline: 1.2857x; 1.0708x over previous
#include <cuda_runtime.h>
#include <cuda_bf16.h>

#define B_CONST 32
#define L_CONST 256
#define H_CONST 512
#define ROWS_PER_WARP   4
#define WARPS_PER_BLOCK 8
#define ROWS_PER_BLOCK  (ROWS_PER_WARP * WARPS_PER_BLOCK)   // 32

// Single fused kernel. Each block serves one batch b and 32 consecutive output
// rows. Prologue: recompute the per-batch inclusive cumsum of durations (1KB,
// L2-hot) with a warp-shuffle scan into shared. Then each warp handles 4
// consecutive rows: binary-search the source index (9 steps -> fully resolved),
// reload the 2KB source row only when the index changes (~87% reuse),
// stream-store (__stcs) the output. Rows past total are zeroed; mask written
// by the first 32 threads.
__global__ void __launch_bounds__(256) fused_kernel(
    const float4* __restrict__ x4,   // [B, L, 128]
    const int*    __restrict__ dur,  // [B, L]
    float4*       __restrict__ out4, // [B, T, 128]
    float*        __restrict__ out_mask, // [B, T]
    int T)
{
    __shared__ int s_csum[L_CONST];
    __shared__ int s_wsum[8];

    int b    = blockIdx.y;
    int tid  = threadIdx.x;
    int lane = tid & 31;
    int w    = tid >> 5;

    // ---- per-batch scan of durations into s_csum (inclusive) ----
    int d = dur[b * L_CONST + tid];
    int v = d;
    #pragma unroll
    for (int off = 1; off < 32; off <<= 1) {
        int n = __shfl_up_sync(0xFFFFFFFFu, v, off);
        if (lane >= off) v += n;
    }
    if (lane == 31) s_wsum[w] = v;
    __syncthreads();
    if (w == 0) {
        int ws = (lane < 8) ? s_wsum[lane] : 0;
        #pragma unroll
        for (int off = 1; off < 8; off <<= 1) {
            int n = __shfl_up_sync(0xFFFFFFFFu, ws, off);
            if (lane >= off) ws += n;
        }
        if (lane < 8) s_wsum[lane] = ws;
    }
    __syncthreads();
    int base = (w > 0) ? s_wsum[w - 1] : 0;
    s_csum[tid] = base + v;
    __syncthreads();

    int total = s_csum[L_CONST - 1];
    int t0_block = blockIdx.x * ROWS_PER_BLOCK;

    // ---- mask for this block's 32 rows ----
    if (tid < ROWS_PER_BLOCK) {
        int tm = t0_block + tid;
        if (tm < T)
            out_mask[(size_t)b * T + tm] = (tm < total) ? 1.0f : 0.0f;
    }

    // ---- expand: one warp per 4 consecutive rows ----
    int t0 = t0_block + w * ROWS_PER_WARP;
    if (t0 >= T) return;

    const float4 z = make_float4(0.f, 0.f, 0.f, 0.f);
    float4 v0 = z, v1 = z, v2 = z, v3 = z;
    int cur = -2;

    float4* dp = out4 + ((size_t)b * T + t0) * 128 + lane;

    #pragma unroll
    for (int r = 0; r < ROWS_PER_WARP; ++r) {
        int t = t0 + r;
        if (t >= T) break;

        int idx;
        if (t >= total) {
            idx = -1;
        } else {
            // searchsorted(csum, t, 'right'): first l with csum[l] > t.
            // [0,256) needs NINE bisection steps to fully resolve (lo==hi).
            int lo = 0, hi = L_CONST;
            #pragma unroll
            for (int step = 0; step < 9; ++step) {
                int mid = (lo + hi) >> 1;
                if (s_csum[mid] <= t) lo = mid + 1; else hi = mid;
            }
            idx = (lo > L_CONST - 1) ? (L_CONST - 1) : lo;
        }

        if (idx != cur) {
            if (idx >= 0) {
                const float4* s = x4 + ((size_t)b * L_CONST + idx) * 128 + lane;
                v0 = __ldg(s);
                v1 = __ldg(s + 32);
                v2 = __ldg(s + 64);
                v3 = __ldg(s + 96);
            } else {
                v0 = z; v1 = z; v2 = z; v3 = z;
            }
            cur = idx;
        }

        __stcs(dp,      v0);
        __stcs(dp + 32, v1);
        __stcs(dp + 64, v2);
        __stcs(dp + 96, v3);
        dp += 128;
    }
}

extern "C" void kernel_launch(void* const* d_in, const int* in_sizes, int n_in,
                              void* d_out, int out_size) {
    const float* x;
    const int*   dur;
    if (in_sizes[0] == B_CONST * L_CONST) {
        dur = (const int*)d_in[0];
        x   = (const float*)d_in[1];
    } else {
        x   = (const float*)d_in[0];
        dur = (const int*)d_in[1];
    }

    int T = out_size / (B_CONST * (H_CONST + 1));

    float* out      = (float*)d_out;
    float* out_mask = out + (size_t)B_CONST * T * H_CONST;

    dim3 grid((T + ROWS_PER_BLOCK - 1) / ROWS_PER_BLOCK, B_CONST);
    fused_kernel<<<grid, 256>>>(
        (const float4*)x, dur, (float4*)out, out_mask, T);
}